// round 13
// baseline (speedup 1.0000x reference)
#include <cuda_runtime.h>
#include <cuda_fp16.h>

#define NN 100000
#define NE 1600000
#define NG 1000
#define NB 98              // scan blocks: 98 * 1024 >= NN

// ---------------- scratch (device globals; 16B-aligned) --------------------
__device__ __align__(16) float g_Z[NN * 64];
__device__ __align__(16) __half g_Z16[NN * 64];   // fp16 message copy of Z
__device__ __align__(16) float g_Pa[NN * 64];
__device__ __align__(16) float g_Pb[NN * 64];
__device__ __align__(16) int g_deg[NN];
__device__ int g_rowstart[NN];
__device__ int g_cursor[NN];
__device__ int g_srclist[NE];
__device__ int g_bsum[128];

// compile-time buffer selection (0 = external input, 1 = g_Pa, 2 = g_Pb)
template <int SEL> __device__ __forceinline__ const float* in_buf(const float* ext);
template <> __device__ __forceinline__ const float* in_buf<0>(const float* ext) { return ext; }
template <> __device__ __forceinline__ const float* in_buf<1>(const float*) { return g_Pa; }
template <> __device__ __forceinline__ const float* in_buf<2>(const float*) { return g_Pb; }
template <int SEL> __device__ __forceinline__ float* out_buf();
template <> __device__ __forceinline__ float* out_buf<1>() { return g_Pa; }
template <> __device__ __forceinline__ float* out_buf<2>() { return g_Pb; }

// ---------------- packed f32x2 helpers (sm_103a) ---------------------------
__device__ __forceinline__ unsigned long long ffma2(
    unsigned long long a, unsigned long long b, unsigned long long c) {
    unsigned long long d;
    asm("fma.rn.f32x2 %0, %1, %2, %3;" : "=l"(d) : "l"(a), "l"(b), "l"(c));
    return d;
}
__device__ __forceinline__ unsigned long long pack2(float x) {
    unsigned long long d;
    asm("mov.b64 %0, {%1, %2};" : "=l"(d) : "f"(x), "f"(x));
    return d;
}
__device__ __forceinline__ float2 unpack2(unsigned long long v) {
    float2 r;
    asm("mov.b64 {%0, %1}, %2;" : "=f"(r.x), "=f"(r.y) : "l"(v));
    return r;
}

// ---------------- half2 <-> uint bit-casts ----------------------------------
__device__ __forceinline__ unsigned h2_to_u(__half2 h) {
    __half2_raw r = *reinterpret_cast<__half2_raw*>(&h);
    return (unsigned)r.x | ((unsigned)r.y << 16);
}
__device__ __forceinline__ __half2 u_to_h2(unsigned u) {
    __half2_raw r;
    r.x = (unsigned short)(u & 0xFFFF);
    r.y = (unsigned short)(u >> 16);
    return *reinterpret_cast<__half2*>(&r);
}

// ---------------- CSR build (edge_index is int32) --------------------------
__global__ void zero_deg_kernel() {
    int i = blockIdx.x * 256 + threadIdx.x;
    if (i < NN) g_deg[i] = 0;
}

// 4 edges per thread (int4 load), 4 atomics in flight
__global__ void __launch_bounds__(256) count_deg_kernel(const int* __restrict__ ei) {
    int t = blockIdx.x * 256 + threadIdx.x;
    if (t * 4 >= NE) return;
    int4 d4 = ((const int4*)(ei + NE))[t];
    if ((unsigned)d4.x < NN) atomicAdd(&g_deg[d4.x], 1);
    if ((unsigned)d4.y < NN) atomicAdd(&g_deg[d4.y], 1);
    if ((unsigned)d4.z < NN) atomicAdd(&g_deg[d4.z], 1);
    if ((unsigned)d4.w < NN) atomicAdd(&g_deg[d4.w], 1);
}

__global__ void __launch_bounds__(256) scanA_kernel() {
    __shared__ int red[256];
    int t = threadIdx.x;
    int base = blockIdx.x * 1024 + t * 4;
    int s = 0;
#pragma unroll
    for (int i = 0; i < 4; i++) {
        int idx = base + i;
        if (idx < NN) s += g_deg[idx];
    }
    red[t] = s;
    __syncthreads();
    for (int off = 128; off > 0; off >>= 1) {
        if (t < off) red[t] += red[t + off];
        __syncthreads();
    }
    if (t == 0) g_bsum[blockIdx.x] = red[0];
}

__global__ void __launch_bounds__(256) scanC_kernel() {
    __shared__ int offsh[256];
    __shared__ int sh[256];
    int t = threadIdx.x;

    offsh[t] = (t < blockIdx.x) ? g_bsum[t] : 0;
    int base = blockIdx.x * 1024 + t * 4;
    int d[4];
    int s = 0;
#pragma unroll
    for (int i = 0; i < 4; i++) {
        int idx = base + i;
        d[i] = (idx < NN) ? g_deg[idx] : 0;
        s += d[i];
    }
    sh[t] = s;
    __syncthreads();
    for (int off = 128; off > 0; off >>= 1) {
        if (t < off) offsh[t] += offsh[t + off];
        __syncthreads();
    }
    for (int off = 1; off < 256; off <<= 1) {
        int v = sh[t];
        int u = (t >= off) ? sh[t - off] : 0;
        __syncthreads();
        sh[t] = v + u;
        __syncthreads();
    }
    int run = offsh[0] + ((t == 0) ? 0 : sh[t - 1]);
#pragma unroll
    for (int i = 0; i < 4; i++) {
        int idx = base + i;
        if (idx < NN) {
            g_rowstart[idx] = run;
            g_cursor[idx] = run;
            run += d[i];
        }
    }
}

__global__ void __launch_bounds__(256) fill_csr_kernel(const int* __restrict__ ei) {
    int t = blockIdx.x * 256 + threadIdx.x;
    if (t * 4 >= NE) return;
    int4 s4 = ((const int4*)ei)[t];
    int4 d4 = ((const int4*)(ei + NE))[t];
    int s[4] = {s4.x, s4.y, s4.z, s4.w};
    int d[4] = {d4.x, d4.y, d4.z, d4.w};
#pragma unroll
    for (int i = 0; i < 4; i++) {
        if ((unsigned)s[i] < NN && (unsigned)d[i] < NN) {
            int pos = atomicAdd(&g_cursor[d[i]], 1);
            if ((unsigned)pos < NE) g_srclist[pos] = s[i];
        }
    }
}

// ---------------- GEMM: Z = A @ W (fp32) + Z16 (fp16 copy) -----------------
// 2 threads per row (cols 0-31 / 32-63): acc[16] ULL = 32 regs -> ~64 total
// regs -> ~4 blocks/SM (vs 12% occ at 130 regs). Same total FFMA2/LDS work;
// A loads duplicated x2 but lane-adjacent same-address (broadcast).
template <int K, int IN_SEL>
__global__ void __launch_bounds__(256) gemm64x2_kernel(
    const float* ext_A, const float* __restrict__ W)
{
    __shared__ ulonglong2 Ws[K * 16];   // K rows x 64 cols (32 f32-pairs)
    for (int i = threadIdx.x; i < K * 16; i += 256)
        Ws[i] = ((const ulonglong2*)W)[i];
    __syncthreads();

    const float* A = in_buf<IN_SEL>(ext_A);
    int row  = blockIdx.x * 128 + (threadIdx.x >> 1);
    int half = threadIdx.x & 1;           // 0: cols 0-31, 1: cols 32-63
    if (row >= NN) return;

    unsigned long long acc[16];
#pragma unroll
    for (int j = 0; j < 16; j++) acc[j] = 0ULL;

    const float4* A4 = (const float4*)(A + (long long)row * K);
#pragma unroll 1
    for (int k4 = 0; k4 < K / 4; k4++) {
        float4 a = A4[k4];
        const float av[4] = {a.x, a.y, a.z, a.w};
#pragma unroll
        for (int kk = 0; kk < 4; kk++) {
            unsigned long long m = pack2(av[kk]);
            const ulonglong2* wr = &Ws[(k4 * 4 + kk) * 16 + half * 8];
#pragma unroll
            for (int j4 = 0; j4 < 8; j4++) {
                ulonglong2 w = wr[j4];
                acc[2 * j4 + 0] = ffma2(m, w.x, acc[2 * j4 + 0]);
                acc[2 * j4 + 1] = ffma2(m, w.y, acc[2 * j4 + 1]);
            }
        }
    }

    float4* Z4 = (float4*)(g_Z + (long long)row * 64 + half * 32);
    uint4*  H4 = (uint4*)(g_Z16 + (long long)row * 64 + half * 32);
#pragma unroll
    for (int j4 = 0; j4 < 8; j4++) {
        float2 lo = unpack2(acc[2 * j4]);
        float2 hi = unpack2(acc[2 * j4 + 1]);
        Z4[j4] = make_float4(lo.x, lo.y, hi.x, hi.y);
    }
#pragma unroll
    for (int j8 = 0; j8 < 4; j8++) {       // 8 halves per uint4
        float2 p0 = unpack2(acc[4 * j8 + 0]);
        float2 p1 = unpack2(acc[4 * j8 + 1]);
        float2 p2 = unpack2(acc[4 * j8 + 2]);
        float2 p3 = unpack2(acc[4 * j8 + 3]);
        uint4 h;
        h.x = h2_to_u(__float22half2_rn(p0));
        h.y = h2_to_u(__float22half2_rn(p1));
        h.z = h2_to_u(__float22half2_rn(p2));
        h.w = h2_to_u(__float22half2_rn(p3));
        H4[j8] = h;
    }
}

// ---- gather: P[n] = relu((1+eps)*Z[n](fp32) + b + sum_in Z16[src](fp16)) --
// 8 threads per node; uint4 fp16 lanes; ILP-4 (the proven 299us config).
template <int OUT_SEL>
__global__ void __launch_bounds__(256) gather_kernel(
    const float* __restrict__ b, const float* __restrict__ epsp)
{
    int gid = blockIdx.x * 256 + threadIdx.x;
    int n = gid >> 3;
    int lane = gid & 7;
    if (n >= NN) return;

    const float4* Z4 = (const float4*)g_Z;
    const uint4*  H4 = (const uint4*)g_Z16;
    float ep = 1.0f + *epsp;
    const float* bp = b + lane * 8;

    float4 z0 = Z4[n * 16 + lane * 2];
    float4 z1 = Z4[n * 16 + lane * 2 + 1];
    float a0 = fmaf(ep, z0.x, bp[0]);
    float a1 = fmaf(ep, z0.y, bp[1]);
    float a2 = fmaf(ep, z0.z, bp[2]);
    float a3 = fmaf(ep, z0.w, bp[3]);
    float a4 = fmaf(ep, z1.x, bp[4]);
    float a5 = fmaf(ep, z1.y, bp[5]);
    float a6 = fmaf(ep, z1.z, bp[6]);
    float a7 = fmaf(ep, z1.w, bp[7]);

    int beg = g_rowstart[n];
    int end = beg + g_deg[n];
    int k = beg;
    for (; k + 4 <= end; k += 4) {
        int s0 = g_srclist[k];
        int s1 = g_srclist[k + 1];
        int s2 = g_srclist[k + 2];
        int s3 = g_srclist[k + 3];
        uint4 h0 = H4[s0 * 8 + lane];
        uint4 h1 = H4[s1 * 8 + lane];
        uint4 h2 = H4[s2 * 8 + lane];
        uint4 h3 = H4[s3 * 8 + lane];
#pragma unroll
        for (int i = 0; i < 4; i++) {
            uint4 h = (i == 0) ? h0 : (i == 1) ? h1 : (i == 2) ? h2 : h3;
            float2 f0 = __half22float2(u_to_h2(h.x));
            float2 f1 = __half22float2(u_to_h2(h.y));
            float2 f2 = __half22float2(u_to_h2(h.z));
            float2 f3 = __half22float2(u_to_h2(h.w));
            a0 += f0.x; a1 += f0.y; a2 += f1.x; a3 += f1.y;
            a4 += f2.x; a5 += f2.y; a6 += f3.x; a7 += f3.y;
        }
    }
    for (; k < end; k++) {
        int s = g_srclist[k];
        uint4 h = H4[s * 8 + lane];
        float2 f0 = __half22float2(u_to_h2(h.x));
        float2 f1 = __half22float2(u_to_h2(h.y));
        float2 f2 = __half22float2(u_to_h2(h.z));
        float2 f3 = __half22float2(u_to_h2(h.w));
        a0 += f0.x; a1 += f0.y; a2 += f1.x; a3 += f1.y;
        a4 += f2.x; a5 += f2.y; a6 += f3.x; a7 += f3.y;
    }

    float4* P4 = (float4*)out_buf<OUT_SEL>();
    P4[n * 16 + lane * 2] = make_float4(fmaxf(a0, 0.0f), fmaxf(a1, 0.0f),
                                        fmaxf(a2, 0.0f), fmaxf(a3, 0.0f));
    P4[n * 16 + lane * 2 + 1] = make_float4(fmaxf(a4, 0.0f), fmaxf(a5, 0.0f),
                                            fmaxf(a6, 0.0f), fmaxf(a7, 0.0f));
}

// ---------------- pool (batch sorted int32) + MLP head ---------------------
__global__ void __launch_bounds__(64) pool_head_kernel(
    const int* __restrict__ batch,
    const float* __restrict__ Wf, const float* __restrict__ bf,
    const float* __restrict__ Wl, const float* __restrict__ bl,
    float* __restrict__ out)
{
    int g = blockIdx.x;
    int t = threadIdx.x;

    int lo = 0, hi = NN;
    while (lo < hi) { int m = (lo + hi) >> 1; if (batch[m] < g) lo = m + 1; else hi = m; }
    int beg = lo;
    lo = beg; hi = NN;
    while (lo < hi) { int m = (lo + hi) >> 1; if (batch[m] < g + 1) lo = m + 1; else hi = m; }
    int end = lo;

    float s = 0.0f;
    for (int n = beg; n < end; n++)
        s += g_Pa[(long long)n * 64 + t];
    float cnt = (float)(end - beg);
    float pooled = s / fmaxf(cnt, 1.0f);

    __shared__ float ps[64];
    __shared__ float ts[10];
    ps[t] = pooled;
    __syncthreads();

    if (t < 10) {
        float acc = bf[t];
        for (int j = 0; j < 64; j++)
            acc = fmaf(ps[j], Wf[j * 10 + t], acc);
        ts[t] = fmaxf(acc, 0.0f);
    }
    __syncthreads();

    if (t == 0) {
        float r = bl[0];
#pragma unroll
        for (int o = 0; o < 10; o++) r = fmaf(ts[o], Wl[o], r);
        out[g] = r;
    }
}

// ---------------- launch ---------------------------------------------------
// gemm1 stays at launch index 3 (the profiler's fixed capture slot) so next
// round's ncu verifies the occupancy fix.
extern "C" void kernel_launch(void* const* d_in, const int* in_sizes, int n_in,
                              void* d_out, int out_size)
{
    const float* x     = (const float*)d_in[0];
    const int*   ei    = (const int*)d_in[1];     // int32 (JAX x64 disabled)
    const int*   batch = (const int*)d_in[2];     // int32, sorted
    const float* W1 = (const float*)d_in[3];
    const float* b1 = (const float*)d_in[4];
    const float* W2 = (const float*)d_in[5];
    const float* b2 = (const float*)d_in[6];
    const float* W3 = (const float*)d_in[7];
    const float* b3 = (const float*)d_in[8];
    const float* Wf = (const float*)d_in[9];
    const float* bf = (const float*)d_in[10];
    const float* Wl = (const float*)d_in[11];
    const float* bl = (const float*)d_in[12];
    const float* e1 = (const float*)d_in[13];
    const float* e2 = (const float*)d_in[14];
    const float* e3 = (const float*)d_in[15];
    float* out = (float*)d_out;

    const int node_grid  = (NN + 255) / 256;           // 391
    const int gemm_grid  = (NN + 127) / 128;           // 782 (2 thr/row, 256 thr/blk)
    const int edge4_grid = (NE / 4 + 255) / 256;       // 1563
    const int gath_grid  = (NN * 8 + 255) / 256;       // 3125

    // CSR by destination; gemm1 interleaved (independent of CSR) so the
    // profiler's fixed capture slot lands on it.
    zero_deg_kernel<<<node_grid, 256>>>();                       // 0
    count_deg_kernel<<<edge4_grid, 256>>>(ei);                   // 1
    scanA_kernel<<<NB, 256>>>();                                 // 2
    gemm64x2_kernel<128, 0><<<gemm_grid, 256>>>(x, W1);          // 3 <- profiled
    scanC_kernel<<<NB, 256>>>();                                 // 4
    fill_csr_kernel<<<edge4_grid, 256>>>(ei);                    // 5

    // Layer 1 aggregate
    gather_kernel<1><<<gath_grid, 256>>>(b1, e1);

    // Layer 2
    gemm64x2_kernel<64, 1><<<gemm_grid, 256>>>(nullptr, W2);
    gather_kernel<2><<<gath_grid, 256>>>(b2, e2);

    // Layer 3
    gemm64x2_kernel<64, 2><<<gemm_grid, 256>>>(nullptr, W3);
    gather_kernel<1><<<gath_grid, 256>>>(b3, e3);

    // Mean-pool Pa per graph + head MLP
    pool_head_kernel<<<NG, 64>>>(batch, Wf, bf, Wl, bl, out);
}

// round 14
// speedup vs baseline: 1.1993x; 1.1993x over previous
#include <cuda_runtime.h>
#include <cuda_fp16.h>

#define NN 100000
#define NE 1600000
#define NG 1000
#define NB 98              // scan blocks: 98 * 1024 >= NN

// ---------------- scratch (device globals; 16B-aligned) --------------------
__device__ __align__(16) float g_Z[NN * 64];
__device__ __align__(16) __half g_Z16[NN * 64];   // fp16 message copy of Z
__device__ __align__(16) float g_Pa[NN * 64];
__device__ __align__(16) float g_Pb[NN * 64];
__device__ __align__(16) int g_deg[NN];
__device__ int g_rowstart[NN];
__device__ int g_cursor[NN];
__device__ int g_srclist[NE];
__device__ int g_bsum[128];

// compile-time buffer selection (0 = external input, 1 = g_Pa, 2 = g_Pb)
template <int SEL> __device__ __forceinline__ const float* in_buf(const float* ext);
template <> __device__ __forceinline__ const float* in_buf<0>(const float* ext) { return ext; }
template <> __device__ __forceinline__ const float* in_buf<1>(const float*) { return g_Pa; }
template <> __device__ __forceinline__ const float* in_buf<2>(const float*) { return g_Pb; }
template <int SEL> __device__ __forceinline__ float* out_buf();
template <> __device__ __forceinline__ float* out_buf<1>() { return g_Pa; }
template <> __device__ __forceinline__ float* out_buf<2>() { return g_Pb; }

// ---------------- packed f32x2 helpers (sm_103a) ---------------------------
__device__ __forceinline__ unsigned long long ffma2(
    unsigned long long a, unsigned long long b, unsigned long long c) {
    unsigned long long d;
    asm("fma.rn.f32x2 %0, %1, %2, %3;" : "=l"(d) : "l"(a), "l"(b), "l"(c));
    return d;
}
__device__ __forceinline__ unsigned long long pack2(float x) {
    unsigned long long d;
    asm("mov.b64 %0, {%1, %2};" : "=l"(d) : "f"(x), "f"(x));
    return d;
}
__device__ __forceinline__ float2 unpack2(unsigned long long v) {
    float2 r;
    asm("mov.b64 {%0, %1}, %2;" : "=f"(r.x), "=f"(r.y) : "l"(v));
    return r;
}

// ---------------- half2 <-> uint bit-casts ----------------------------------
__device__ __forceinline__ unsigned h2_to_u(__half2 h) {
    __half2_raw r = *reinterpret_cast<__half2_raw*>(&h);
    return (unsigned)r.x | ((unsigned)r.y << 16);
}
__device__ __forceinline__ __half2 u_to_h2(unsigned u) {
    __half2_raw r;
    r.x = (unsigned short)(u & 0xFFFF);
    r.y = (unsigned short)(u >> 16);
    return *reinterpret_cast<__half2*>(&r);
}

// ---------------- CSR build (edge_index is int32) --------------------------
__global__ void zero_deg_kernel() {
    int i = blockIdx.x * 256 + threadIdx.x;
    if (i < NN) g_deg[i] = 0;
}

// 4 edges per thread (int4 load), 4 atomics in flight
__global__ void __launch_bounds__(256) count_deg_kernel(const int* __restrict__ ei) {
    int t = blockIdx.x * 256 + threadIdx.x;
    if (t * 4 >= NE) return;
    int4 d4 = ((const int4*)(ei + NE))[t];
    if ((unsigned)d4.x < NN) atomicAdd(&g_deg[d4.x], 1);
    if ((unsigned)d4.y < NN) atomicAdd(&g_deg[d4.y], 1);
    if ((unsigned)d4.z < NN) atomicAdd(&g_deg[d4.z], 1);
    if ((unsigned)d4.w < NN) atomicAdd(&g_deg[d4.w], 1);
}

__global__ void __launch_bounds__(256) scanA_kernel() {
    __shared__ int red[256];
    int t = threadIdx.x;
    int base = blockIdx.x * 1024 + t * 4;
    int s = 0;
#pragma unroll
    for (int i = 0; i < 4; i++) {
        int idx = base + i;
        if (idx < NN) s += g_deg[idx];
    }
    red[t] = s;
    __syncthreads();
    for (int off = 128; off > 0; off >>= 1) {
        if (t < off) red[t] += red[t + off];
        __syncthreads();
    }
    if (t == 0) g_bsum[blockIdx.x] = red[0];
}

__global__ void __launch_bounds__(256) scanC_kernel() {
    __shared__ int offsh[256];
    __shared__ int sh[256];
    int t = threadIdx.x;

    offsh[t] = (t < blockIdx.x) ? g_bsum[t] : 0;
    int base = blockIdx.x * 1024 + t * 4;
    int d[4];
    int s = 0;
#pragma unroll
    for (int i = 0; i < 4; i++) {
        int idx = base + i;
        d[i] = (idx < NN) ? g_deg[idx] : 0;
        s += d[i];
    }
    sh[t] = s;
    __syncthreads();
    for (int off = 128; off > 0; off >>= 1) {
        if (t < off) offsh[t] += offsh[t + off];
        __syncthreads();
    }
    for (int off = 1; off < 256; off <<= 1) {
        int v = sh[t];
        int u = (t >= off) ? sh[t - off] : 0;
        __syncthreads();
        sh[t] = v + u;
        __syncthreads();
    }
    int run = offsh[0] + ((t == 0) ? 0 : sh[t - 1]);
#pragma unroll
    for (int i = 0; i < 4; i++) {
        int idx = base + i;
        if (idx < NN) {
            g_rowstart[idx] = run;
            g_cursor[idx] = run;
            run += d[i];
        }
    }
}

__global__ void __launch_bounds__(256) fill_csr_kernel(const int* __restrict__ ei) {
    int t = blockIdx.x * 256 + threadIdx.x;
    if (t * 4 >= NE) return;
    int4 s4 = ((const int4*)ei)[t];
    int4 d4 = ((const int4*)(ei + NE))[t];
    int s[4] = {s4.x, s4.y, s4.z, s4.w};
    int d[4] = {d4.x, d4.y, d4.z, d4.w};
#pragma unroll
    for (int i = 0; i < 4; i++) {
        if ((unsigned)s[i] < NN && (unsigned)d[i] < NN) {
            int pos = atomicAdd(&g_cursor[d[i]], 1);
            if ((unsigned)pos < NE) g_srclist[pos] = s[i];
        }
    }
}

// ---------------- GEMM: Z = A @ W (fp32) + Z16 (fp16 copy) -----------------
// WARP-level column split: warps 0-3 -> cols 0-31, warps 4-7 -> cols 32-63,
// one row per lane. Every warp's LDS stays single-address broadcast
// (1 wavefront, unlike round-13's intra-warp interleave = 2 wavefronts).
// acc[16] ULL = 32 regs -> ~70 total -> ~3 blocks/SM (occ ~33% vs 12%).
template <int K, int IN_SEL>
__global__ void __launch_bounds__(256) gemm64x2_kernel(
    const float* ext_A, const float* __restrict__ W)
{
    __shared__ ulonglong2 Ws[K * 16];   // K rows x 64 cols (32 f32-pairs)
    for (int i = threadIdx.x; i < K * 16; i += 256)
        Ws[i] = ((const ulonglong2*)W)[i];
    __syncthreads();

    const float* A = in_buf<IN_SEL>(ext_A);
    int wid  = threadIdx.x >> 5;          // 0..7
    int lane = threadIdx.x & 31;
    int half = wid >> 2;                  // warps 0-3: cols 0-31; 4-7: cols 32-63
    int row  = blockIdx.x * 128 + (wid & 3) * 32 + lane;
    if (row >= NN) return;

    unsigned long long acc[16];
#pragma unroll
    for (int j = 0; j < 16; j++) acc[j] = 0ULL;

    const float4* A4 = (const float4*)(A + (long long)row * K);
#pragma unroll 1
    for (int k4 = 0; k4 < K / 4; k4++) {
        float4 a = A4[k4];
        const float av[4] = {a.x, a.y, a.z, a.w};
#pragma unroll
        for (int kk = 0; kk < 4; kk++) {
            unsigned long long m = pack2(av[kk]);
            const ulonglong2* wr = &Ws[(k4 * 4 + kk) * 16 + half * 8];  // warp-uniform
#pragma unroll
            for (int j4 = 0; j4 < 8; j4++) {
                ulonglong2 w = wr[j4];
                acc[2 * j4 + 0] = ffma2(m, w.x, acc[2 * j4 + 0]);
                acc[2 * j4 + 1] = ffma2(m, w.y, acc[2 * j4 + 1]);
            }
        }
    }

    float4* Z4 = (float4*)(g_Z + (long long)row * 64 + half * 32);
    uint4*  H4 = (uint4*)(g_Z16 + (long long)row * 64 + half * 32);
#pragma unroll
    for (int j4 = 0; j4 < 8; j4++) {
        float2 lo = unpack2(acc[2 * j4]);
        float2 hi = unpack2(acc[2 * j4 + 1]);
        Z4[j4] = make_float4(lo.x, lo.y, hi.x, hi.y);
    }
#pragma unroll
    for (int j8 = 0; j8 < 4; j8++) {       // 8 halves per uint4
        float2 p0 = unpack2(acc[4 * j8 + 0]);
        float2 p1 = unpack2(acc[4 * j8 + 1]);
        float2 p2 = unpack2(acc[4 * j8 + 2]);
        float2 p3 = unpack2(acc[4 * j8 + 3]);
        uint4 h;
        h.x = h2_to_u(__float22half2_rn(p0));
        h.y = h2_to_u(__float22half2_rn(p1));
        h.z = h2_to_u(__float22half2_rn(p2));
        h.w = h2_to_u(__float22half2_rn(p3));
        H4[j8] = h;
    }
}

// ---- gather: P[n] = relu((1+eps)*Z[n](fp32) + b + sum_in Z16[src](fp16)) --
// 8 threads per node; uint4 fp16 lanes; ILP-4 (the proven 299us config).
template <int OUT_SEL>
__global__ void __launch_bounds__(256) gather_kernel(
    const float* __restrict__ b, const float* __restrict__ epsp)
{
    int gid = blockIdx.x * 256 + threadIdx.x;
    int n = gid >> 3;
    int lane = gid & 7;
    if (n >= NN) return;

    const float4* Z4 = (const float4*)g_Z;
    const uint4*  H4 = (const uint4*)g_Z16;
    float ep = 1.0f + *epsp;
    const float* bp = b + lane * 8;

    float4 z0 = Z4[n * 16 + lane * 2];
    float4 z1 = Z4[n * 16 + lane * 2 + 1];
    float a0 = fmaf(ep, z0.x, bp[0]);
    float a1 = fmaf(ep, z0.y, bp[1]);
    float a2 = fmaf(ep, z0.z, bp[2]);
    float a3 = fmaf(ep, z0.w, bp[3]);
    float a4 = fmaf(ep, z1.x, bp[4]);
    float a5 = fmaf(ep, z1.y, bp[5]);
    float a6 = fmaf(ep, z1.z, bp[6]);
    float a7 = fmaf(ep, z1.w, bp[7]);

    int beg = g_rowstart[n];
    int end = beg + g_deg[n];
    int k = beg;
    for (; k + 4 <= end; k += 4) {
        int s0 = g_srclist[k];
        int s1 = g_srclist[k + 1];
        int s2 = g_srclist[k + 2];
        int s3 = g_srclist[k + 3];
        uint4 h0 = H4[s0 * 8 + lane];
        uint4 h1 = H4[s1 * 8 + lane];
        uint4 h2 = H4[s2 * 8 + lane];
        uint4 h3 = H4[s3 * 8 + lane];
#pragma unroll
        for (int i = 0; i < 4; i++) {
            uint4 h = (i == 0) ? h0 : (i == 1) ? h1 : (i == 2) ? h2 : h3;
            float2 f0 = __half22float2(u_to_h2(h.x));
            float2 f1 = __half22float2(u_to_h2(h.y));
            float2 f2 = __half22float2(u_to_h2(h.z));
            float2 f3 = __half22float2(u_to_h2(h.w));
            a0 += f0.x; a1 += f0.y; a2 += f1.x; a3 += f1.y;
            a4 += f2.x; a5 += f2.y; a6 += f3.x; a7 += f3.y;
        }
    }
    for (; k < end; k++) {
        int s = g_srclist[k];
        uint4 h = H4[s * 8 + lane];
        float2 f0 = __half22float2(u_to_h2(h.x));
        float2 f1 = __half22float2(u_to_h2(h.y));
        float2 f2 = __half22float2(u_to_h2(h.z));
        float2 f3 = __half22float2(u_to_h2(h.w));
        a0 += f0.x; a1 += f0.y; a2 += f1.x; a3 += f1.y;
        a4 += f2.x; a5 += f2.y; a6 += f3.x; a7 += f3.y;
    }

    float4* P4 = (float4*)out_buf<OUT_SEL>();
    P4[n * 16 + lane * 2] = make_float4(fmaxf(a0, 0.0f), fmaxf(a1, 0.0f),
                                        fmaxf(a2, 0.0f), fmaxf(a3, 0.0f));
    P4[n * 16 + lane * 2 + 1] = make_float4(fmaxf(a4, 0.0f), fmaxf(a5, 0.0f),
                                            fmaxf(a6, 0.0f), fmaxf(a7, 0.0f));
}

// ---------------- pool (batch sorted int32) + MLP head ---------------------
__global__ void __launch_bounds__(64) pool_head_kernel(
    const int* __restrict__ batch,
    const float* __restrict__ Wf, const float* __restrict__ bf,
    const float* __restrict__ Wl, const float* __restrict__ bl,
    float* __restrict__ out)
{
    int g = blockIdx.x;
    int t = threadIdx.x;

    int lo = 0, hi = NN;
    while (lo < hi) { int m = (lo + hi) >> 1; if (batch[m] < g) lo = m + 1; else hi = m; }
    int beg = lo;
    lo = beg; hi = NN;
    while (lo < hi) { int m = (lo + hi) >> 1; if (batch[m] < g + 1) lo = m + 1; else hi = m; }
    int end = lo;

    float s = 0.0f;
    for (int n = beg; n < end; n++)
        s += g_Pa[(long long)n * 64 + t];
    float cnt = (float)(end - beg);
    float pooled = s / fmaxf(cnt, 1.0f);

    __shared__ float ps[64];
    __shared__ float ts[10];
    ps[t] = pooled;
    __syncthreads();

    if (t < 10) {
        float acc = bf[t];
        for (int j = 0; j < 64; j++)
            acc = fmaf(ps[j], Wf[j * 10 + t], acc);
        ts[t] = fmaxf(acc, 0.0f);
    }
    __syncthreads();

    if (t == 0) {
        float r = bl[0];
#pragma unroll
        for (int o = 0; o < 10; o++) r = fmaf(ts[o], Wl[o], r);
        out[g] = r;
    }
}

// ---------------- launch ---------------------------------------------------
// gemm1 stays at launch index 3 (the profiler's fixed capture slot) so next
// round's ncu verifies the warp-split fix (expect occ ~33%, L1 ~60%, dur ~50us).
extern "C" void kernel_launch(void* const* d_in, const int* in_sizes, int n_in,
                              void* d_out, int out_size)
{
    const float* x     = (const float*)d_in[0];
    const int*   ei    = (const int*)d_in[1];     // int32 (JAX x64 disabled)
    const int*   batch = (const int*)d_in[2];     // int32, sorted
    const float* W1 = (const float*)d_in[3];
    const float* b1 = (const float*)d_in[4];
    const float* W2 = (const float*)d_in[5];
    const float* b2 = (const float*)d_in[6];
    const float* W3 = (const float*)d_in[7];
    const float* b3 = (const float*)d_in[8];
    const float* Wf = (const float*)d_in[9];
    const float* bf = (const float*)d_in[10];
    const float* Wl = (const float*)d_in[11];
    const float* bl = (const float*)d_in[12];
    const float* e1 = (const float*)d_in[13];
    const float* e2 = (const float*)d_in[14];
    const float* e3 = (const float*)d_in[15];
    float* out = (float*)d_out;

    const int node_grid  = (NN + 255) / 256;           // 391
    const int gemm_grid  = (NN + 127) / 128;           // 782 (128 rows/block)
    const int edge4_grid = (NE / 4 + 255) / 256;       // 1563
    const int gath_grid  = (NN * 8 + 255) / 256;       // 3125

    // CSR by destination; gemm1 interleaved (independent of CSR) so the
    // profiler's fixed capture slot lands on it.
    zero_deg_kernel<<<node_grid, 256>>>();                       // 0
    count_deg_kernel<<<edge4_grid, 256>>>(ei);                   // 1
    scanA_kernel<<<NB, 256>>>();                                 // 2
    gemm64x2_kernel<128, 0><<<gemm_grid, 256>>>(x, W1);          // 3 <- profiled
    scanC_kernel<<<NB, 256>>>();                                 // 4
    fill_csr_kernel<<<edge4_grid, 256>>>(ei);                    // 5

    // Layer 1 aggregate
    gather_kernel<1><<<gath_grid, 256>>>(b1, e1);

    // Layer 2
    gemm64x2_kernel<64, 1><<<gemm_grid, 256>>>(nullptr, W2);
    gather_kernel<2><<<gath_grid, 256>>>(b2, e2);

    // Layer 3
    gemm64x2_kernel<64, 2><<<gemm_grid, 256>>>(nullptr, W3);
    gather_kernel<1><<<gath_grid, 256>>>(b3, e3);

    // Mean-pool Pa per graph + head MLP
    pool_head_kernel<<<NG, 64>>>(batch, Wf, bf, Wl, bl, out);
}

// round 16
// speedup vs baseline: 2.0641x; 1.7211x over previous
#include <cuda_runtime.h>
#include <cuda_fp16.h>
#include <cstdint>

#define NN 100000
#define NE 1600000
#define NG 1000
#define NB 98              // scan blocks: 98 * 1024 >= NN

// ---------------- scratch (device globals; 16B-aligned) --------------------
__device__ __align__(16) __half g_X16[NN * 128];  // fp16 copy of x
__device__ __align__(16) __half g_P16[NN * 64];   // fp16 layer activations (GEMM input)
__device__ __align__(16) float  g_Z[NN * 64];     // fp32 GEMM output (self term)
__device__ __align__(16) __half g_Z16[NN * 64];   // fp16 GEMM output (messages)
__device__ __align__(16) float  g_Pa[NN * 64];    // fp32 layer-3 output (pool input)
__device__ __align__(16) __half g_W1h[128 * 64];
__device__ __align__(16) __half g_W2h[64 * 64];
__device__ __align__(16) __half g_W3h[64 * 64];
__device__ __align__(16) int g_deg[NN];
__device__ int g_rowstart[NN];
__device__ int g_cursor[NN];
__device__ int g_srclist[NE];
__device__ int g_bsum[128];

template <int S> __device__ __forceinline__ const __half* a16_buf();
template <> __device__ __forceinline__ const __half* a16_buf<0>() { return g_X16; }
template <> __device__ __forceinline__ const __half* a16_buf<1>() { return g_P16; }
template <int S> __device__ __forceinline__ const __half* w16_buf();
template <> __device__ __forceinline__ const __half* w16_buf<0>() { return g_W1h; }
template <> __device__ __forceinline__ const __half* w16_buf<1>() { return g_W2h; }
template <> __device__ __forceinline__ const __half* w16_buf<2>() { return g_W3h; }

// ---------------- half2 <-> uint bit-casts ----------------------------------
__device__ __forceinline__ unsigned h2_to_u(__half2 h) {
    __half2_raw r = *reinterpret_cast<__half2_raw*>(&h);
    return (unsigned)r.x | ((unsigned)r.y << 16);
}
__device__ __forceinline__ __half2 u_to_h2(unsigned u) {
    __half2_raw r;
    r.x = (unsigned short)(u & 0xFFFF);
    r.y = (unsigned short)(u >> 16);
    return *reinterpret_cast<__half2*>(&r);
}
__device__ __forceinline__ unsigned f2_to_h2u(float a, float b) {
    return h2_to_u(__float22half2_rn(make_float2(a, b)));
}
__device__ __forceinline__ uint32_t smem_u32(const void* p) {
    uint32_t r;
    asm("{ .reg .u64 t; cvta.to.shared.u64 t, %1; cvt.u32.u64 %0, t; }"
        : "=r"(r) : "l"(p));
    return r;
}

// ---------------- converts --------------------------------------------------
__global__ void __launch_bounds__(256) convert_x_kernel(const float* __restrict__ x) {
    int t = blockIdx.x * 256 + threadIdx.x;
    long long i = (long long)t * 8;
    if (i >= (long long)NN * 128) return;
    const float4* s = (const float4*)(x + i);
    float4 v0 = s[0], v1 = s[1];
    uint4 h;
    h.x = f2_to_h2u(v0.x, v0.y);
    h.y = f2_to_h2u(v0.z, v0.w);
    h.z = f2_to_h2u(v1.x, v1.y);
    h.w = f2_to_h2u(v1.z, v1.w);
    *(uint4*)(g_X16 + i) = h;
}

__global__ void __launch_bounds__(256) convert_w_kernel(
    const float* __restrict__ W1, const float* __restrict__ W2,
    const float* __restrict__ W3) {
    int i = blockIdx.x * 256 + threadIdx.x;
    if (i < 128 * 64) g_W1h[i] = __float2half_rn(W1[i]);
    else if (i < 128 * 64 + 64 * 64) g_W2h[i - 128 * 64] = __float2half_rn(W2[i - 128 * 64]);
    else if (i < 128 * 64 + 2 * 64 * 64) g_W3h[i - 128 * 64 - 64 * 64] = __float2half_rn(W3[i - 128 * 64 - 64 * 64]);
}

// ---------------- CSR build (edge_index is int32) --------------------------
__global__ void zero_deg_kernel() {
    int i = blockIdx.x * 256 + threadIdx.x;
    if (i < NN) g_deg[i] = 0;
}

__global__ void __launch_bounds__(256) count_deg_kernel(const int* __restrict__ ei) {
    int t = blockIdx.x * 256 + threadIdx.x;
    if (t * 4 >= NE) return;
    int4 d4 = ((const int4*)(ei + NE))[t];
    if ((unsigned)d4.x < NN) atomicAdd(&g_deg[d4.x], 1);
    if ((unsigned)d4.y < NN) atomicAdd(&g_deg[d4.y], 1);
    if ((unsigned)d4.z < NN) atomicAdd(&g_deg[d4.z], 1);
    if ((unsigned)d4.w < NN) atomicAdd(&g_deg[d4.w], 1);
}

__global__ void __launch_bounds__(256) scanA_kernel() {
    __shared__ int red[256];
    int t = threadIdx.x;
    int base = blockIdx.x * 1024 + t * 4;
    int s = 0;
#pragma unroll
    for (int i = 0; i < 4; i++) {
        int idx = base + i;
        if (idx < NN) s += g_deg[idx];
    }
    red[t] = s;
    __syncthreads();
    for (int off = 128; off > 0; off >>= 1) {
        if (t < off) red[t] += red[t + off];
        __syncthreads();
    }
    if (t == 0) g_bsum[blockIdx.x] = red[0];
}

__global__ void __launch_bounds__(256) scanC_kernel() {
    __shared__ int offsh[256];
    __shared__ int sh[256];
    int t = threadIdx.x;

    offsh[t] = (t < blockIdx.x) ? g_bsum[t] : 0;
    int base = blockIdx.x * 1024 + t * 4;
    int d[4];
    int s = 0;
#pragma unroll
    for (int i = 0; i < 4; i++) {
        int idx = base + i;
        d[i] = (idx < NN) ? g_deg[idx] : 0;
        s += d[i];
    }
    sh[t] = s;
    __syncthreads();
    for (int off = 128; off > 0; off >>= 1) {
        if (t < off) offsh[t] += offsh[t + off];
        __syncthreads();
    }
    for (int off = 1; off < 256; off <<= 1) {
        int v = sh[t];
        int u = (t >= off) ? sh[t - off] : 0;
        __syncthreads();
        sh[t] = v + u;
        __syncthreads();
    }
    int run = offsh[0] + ((t == 0) ? 0 : sh[t - 1]);
#pragma unroll
    for (int i = 0; i < 4; i++) {
        int idx = base + i;
        if (idx < NN) {
            g_rowstart[idx] = run;
            g_cursor[idx] = run;
            run += d[i];
        }
    }
}

__global__ void __launch_bounds__(256) fill_csr_kernel(const int* __restrict__ ei) {
    int t = blockIdx.x * 256 + threadIdx.x;
    if (t * 4 >= NE) return;
    int4 s4 = ((const int4*)ei)[t];
    int4 d4 = ((const int4*)(ei + NE))[t];
    int s[4] = {s4.x, s4.y, s4.z, s4.w};
    int d[4] = {d4.x, d4.y, d4.z, d4.w};
#pragma unroll
    for (int i = 0; i < 4; i++) {
        if ((unsigned)s[i] < NN && (unsigned)d[i] < NN) {
            int pos = atomicAdd(&g_cursor[d[i]], 1);
            if ((unsigned)pos < NE) g_srclist[pos] = s[i];
        }
    }
}

// ---------------- GEMM via HMMA: Z = A(fp16) @ W(fp16), fp32 accum ---------
// Block: 128 rows x 64 cols. 8 warps x (16 rows x 64 cols).
// A tile + W staged in smem with 16B-chunk XOR swizzle (conflict-free ldmatrix).
// Epilogue writes g_Z (fp32) and g_Z16 (fp16).
template <int K, int ASEL, int WSEL>
__global__ void __launch_bounds__(256) gemm_mma_kernel() {
    constexpr int CPR = K / 8;                 // 16B chunks per A row
    __shared__ uint4 As[128 * CPR];            // swizzled A tile
    __shared__ uint4 Ws[K * 8];                // swizzled W (64 cols = 8 chunks/row)

    const uint4* Ag = (const uint4*)a16_buf<ASEL>();
    const uint4* Wg = (const uint4*)w16_buf<WSEL>();

    int tid = threadIdx.x;
    int row0 = blockIdx.x * 128;

    // cooperative fills (coalesced), swizzle: chunk ^= (row & 7)
    for (int i = tid; i < 128 * CPR; i += 256) {
        int r = i / CPR, c = i % CPR;
        int gr = row0 + r;
        uint4 v = make_uint4(0u, 0u, 0u, 0u);
        if (gr < NN) v = Ag[gr * CPR + c];
        As[r * CPR + (c ^ (r & 7))] = v;
    }
    for (int i = tid; i < K * 8; i += 256) {
        int k = i / 8, c = i % 8;
        Ws[k * 8 + (c ^ (k & 7))] = Wg[i];
    }
    __syncthreads();

    int wid = tid >> 5, lane = tid & 31;
    int wrow = wid * 16;                       // local row base of this warp

    float acc[8][4];
#pragma unroll
    for (int t = 0; t < 8; t++)
#pragma unroll
        for (int j = 0; j < 4; j++) acc[t][j] = 0.0f;

    uint32_t As_base = smem_u32(As);
    uint32_t Ws_base = smem_u32(Ws);

    int ar = wrow + (lane & 15);               // A fragment row (local)
#pragma unroll
    for (int k16 = 0; k16 < K / 16; k16++) {
        int kc = k16 * 2 + (lane >> 4);        // 16B chunk within A row
        uint32_t aaddr = As_base + (ar * CPR + (kc ^ (ar & 7))) * 16;
        uint32_t a0, a1, a2, a3;
        asm volatile("ldmatrix.sync.aligned.m8n8.x4.shared.b16 {%0,%1,%2,%3}, [%4];"
                     : "=r"(a0), "=r"(a1), "=r"(a2), "=r"(a3) : "r"(aaddr));
        int kk = k16 * 16 + (lane & 15);       // W row for this lane's B address
#pragma unroll
        for (int nt = 0; nt < 8; nt++) {
            uint32_t baddr = Ws_base + (kk * 8 + (nt ^ (kk & 7))) * 16;
            uint32_t b0, b1;
            asm volatile("ldmatrix.sync.aligned.m8n8.x2.trans.shared.b16 {%0,%1}, [%2];"
                         : "=r"(b0), "=r"(b1) : "r"(baddr));
            asm volatile("mma.sync.aligned.m16n8k16.row.col.f32.f16.f16.f32 "
                         "{%0,%1,%2,%3}, {%4,%5,%6,%7}, {%8,%9}, {%0,%1,%2,%3};"
                         : "+f"(acc[nt][0]), "+f"(acc[nt][1]),
                           "+f"(acc[nt][2]), "+f"(acc[nt][3])
                         : "r"(a0), "r"(a1), "r"(a2), "r"(a3), "r"(b0), "r"(b1));
        }
    }

    // epilogue: lane -> (row = lane>>2 [+8], col = (lane&3)*2) per n-tile
    int gr0 = row0 + wrow + (lane >> 2);
    int gr1 = gr0 + 8;
    int col = (lane & 3) * 2;
#pragma unroll
    for (int nt = 0; nt < 8; nt++) {
        int cc = nt * 8 + col;
        if (gr0 < NN) {
            *(float2*)(g_Z + gr0 * 64 + cc) = make_float2(acc[nt][0], acc[nt][1]);
            *(unsigned*)((__half*)g_Z16 + gr0 * 64 + cc) = f2_to_h2u(acc[nt][0], acc[nt][1]);
        }
        if (gr1 < NN) {
            *(float2*)(g_Z + gr1 * 64 + cc) = make_float2(acc[nt][2], acc[nt][3]);
            *(unsigned*)((__half*)g_Z16 + gr1 * 64 + cc) = f2_to_h2u(acc[nt][2], acc[nt][3]);
        }
    }
}

// ---- gather: P[n] = relu((1+eps)*Z[n](fp32) + b + sum_in Z16[src](fp16)) --
// 8 threads per node; uint4 fp16 lanes; ILP-4 (the proven config).
// OUT16=1 -> fp16 g_P16 (next GEMM input); OUT16=0 -> fp32 g_Pa (pool input).
template <int OUT16>
__global__ void __launch_bounds__(256) gather_kernel(
    const float* __restrict__ b, const float* __restrict__ epsp)
{
    int gid = blockIdx.x * 256 + threadIdx.x;
    int n = gid >> 3;
    int lane = gid & 7;
    if (n >= NN) return;

    const float4* Z4 = (const float4*)g_Z;
    const uint4*  H4 = (const uint4*)g_Z16;
    float ep = 1.0f + *epsp;
    const float* bp = b + lane * 8;

    float4 z0 = Z4[n * 16 + lane * 2];
    float4 z1 = Z4[n * 16 + lane * 2 + 1];
    float a0 = fmaf(ep, z0.x, bp[0]);
    float a1 = fmaf(ep, z0.y, bp[1]);
    float a2 = fmaf(ep, z0.z, bp[2]);
    float a3 = fmaf(ep, z0.w, bp[3]);
    float a4 = fmaf(ep, z1.x, bp[4]);
    float a5 = fmaf(ep, z1.y, bp[5]);
    float a6 = fmaf(ep, z1.z, bp[6]);
    float a7 = fmaf(ep, z1.w, bp[7]);

    int beg = g_rowstart[n];
    int end = beg + g_deg[n];
    int k = beg;
    for (; k + 4 <= end; k += 4) {
        int s0 = g_srclist[k];
        int s1 = g_srclist[k + 1];
        int s2 = g_srclist[k + 2];
        int s3 = g_srclist[k + 3];
        uint4 h0 = H4[s0 * 8 + lane];
        uint4 h1 = H4[s1 * 8 + lane];
        uint4 h2 = H4[s2 * 8 + lane];
        uint4 h3 = H4[s3 * 8 + lane];
#pragma unroll
        for (int i = 0; i < 4; i++) {
            uint4 h = (i == 0) ? h0 : (i == 1) ? h1 : (i == 2) ? h2 : h3;
            float2 f0 = __half22float2(u_to_h2(h.x));
            float2 f1 = __half22float2(u_to_h2(h.y));
            float2 f2 = __half22float2(u_to_h2(h.z));
            float2 f3 = __half22float2(u_to_h2(h.w));
            a0 += f0.x; a1 += f0.y; a2 += f1.x; a3 += f1.y;
            a4 += f2.x; a5 += f2.y; a6 += f3.x; a7 += f3.y;
        }
    }
    for (; k < end; k++) {
        int s = g_srclist[k];
        uint4 h = H4[s * 8 + lane];
        float2 f0 = __half22float2(u_to_h2(h.x));
        float2 f1 = __half22float2(u_to_h2(h.y));
        float2 f2 = __half22float2(u_to_h2(h.z));
        float2 f3 = __half22float2(u_to_h2(h.w));
        a0 += f0.x; a1 += f0.y; a2 += f1.x; a3 += f1.y;
        a4 += f2.x; a5 += f2.y; a6 += f3.x; a7 += f3.y;
    }

    a0 = fmaxf(a0, 0.0f); a1 = fmaxf(a1, 0.0f);
    a2 = fmaxf(a2, 0.0f); a3 = fmaxf(a3, 0.0f);
    a4 = fmaxf(a4, 0.0f); a5 = fmaxf(a5, 0.0f);
    a6 = fmaxf(a6, 0.0f); a7 = fmaxf(a7, 0.0f);

    if (OUT16) {
        uint4 h;
        h.x = f2_to_h2u(a0, a1);
        h.y = f2_to_h2u(a2, a3);
        h.z = f2_to_h2u(a4, a5);
        h.w = f2_to_h2u(a6, a7);
        ((uint4*)g_P16)[n * 8 + lane] = h;
    } else {
        float4* P4 = (float4*)g_Pa;
        P4[n * 16 + lane * 2] = make_float4(a0, a1, a2, a3);
        P4[n * 16 + lane * 2 + 1] = make_float4(a4, a5, a6, a7);
    }
}

// ---------------- pool (batch sorted int32) + MLP head ---------------------
__global__ void __launch_bounds__(64) pool_head_kernel(
    const int* __restrict__ batch,
    const float* __restrict__ Wf, const float* __restrict__ bf,
    const float* __restrict__ Wl, const float* __restrict__ bl,
    float* __restrict__ out)
{
    int g = blockIdx.x;
    int t = threadIdx.x;

    int lo = 0, hi = NN;
    while (lo < hi) { int m = (lo + hi) >> 1; if (batch[m] < g) lo = m + 1; else hi = m; }
    int beg = lo;
    lo = beg; hi = NN;
    while (lo < hi) { int m = (lo + hi) >> 1; if (batch[m] < g + 1) lo = m + 1; else hi = m; }
    int end = lo;

    float s = 0.0f;
    for (int n = beg; n < end; n++)
        s += g_Pa[(long long)n * 64 + t];
    float cnt = (float)(end - beg);
    float pooled = s / fmaxf(cnt, 1.0f);

    __shared__ float ps[64];
    __shared__ float ts[10];
    ps[t] = pooled;
    __syncthreads();

    if (t < 10) {
        float acc = bf[t];
        for (int j = 0; j < 64; j++)
            acc = fmaf(ps[j], Wf[j * 10 + t], acc);
        ts[t] = fmaxf(acc, 0.0f);
    }
    __syncthreads();

    if (t == 0) {
        float r = bl[0];
#pragma unroll
        for (int o = 0; o < 10; o++) r = fmaf(ts[o], Wl[o], r);
        out[g] = r;
    }
}

// ---------------- launch ---------------------------------------------------
// gemm1 at launch index 3 = the profiler's fixed capture slot.
extern "C" void kernel_launch(void* const* d_in, const int* in_sizes, int n_in,
                              void* d_out, int out_size)
{
    const float* x     = (const float*)d_in[0];
    const int*   ei    = (const int*)d_in[1];     // int32 (JAX x64 disabled)
    const int*   batch = (const int*)d_in[2];     // int32, sorted
    const float* W1 = (const float*)d_in[3];
    const float* b1 = (const float*)d_in[4];
    const float* W2 = (const float*)d_in[5];
    const float* b2 = (const float*)d_in[6];
    const float* W3 = (const float*)d_in[7];
    const float* b3 = (const float*)d_in[8];
    const float* Wf = (const float*)d_in[9];
    const float* bf = (const float*)d_in[10];
    const float* Wl = (const float*)d_in[11];
    const float* bl = (const float*)d_in[12];
    const float* e1 = (const float*)d_in[13];
    const float* e2 = (const float*)d_in[14];
    const float* e3 = (const float*)d_in[15];
    float* out = (float*)d_out;

    const int node_grid  = (NN + 255) / 256;           // 391
    const int gemm_grid  = (NN + 127) / 128;           // 782
    const int edge4_grid = (NE / 4 + 255) / 256;       // 1563
    const int gath_grid  = (NN * 8 + 255) / 256;       // 3125
    const int cvtx_grid  = (NN * 128 / 8 + 255) / 256; // 6250

    convert_x_kernel<<<cvtx_grid, 256>>>(x);                     // 0
    convert_w_kernel<<<64, 256>>>(W1, W2, W3);                   // 1
    zero_deg_kernel<<<node_grid, 256>>>();                       // 2
    gemm_mma_kernel<128, 0, 0><<<gemm_grid, 256>>>();            // 3 <- profiled
    count_deg_kernel<<<edge4_grid, 256>>>(ei);                   // 4
    scanA_kernel<<<NB, 256>>>();                                 // 5
    scanC_kernel<<<NB, 256>>>();                                 // 6
    fill_csr_kernel<<<edge4_grid, 256>>>(ei);                    // 7

    // Layer 1 aggregate -> fp16 P16
    gather_kernel<1><<<gath_grid, 256>>>(b1, e1);

    // Layer 2
    gemm_mma_kernel<64, 1, 1><<<gemm_grid, 256>>>();
    gather_kernel<1><<<gath_grid, 256>>>(b2, e2);

    // Layer 3 -> fp32 Pa for pooling
    gemm_mma_kernel<64, 1, 2><<<gemm_grid, 256>>>();
    gather_kernel<0><<<gath_grid, 256>>>(b3, e3);

    // Mean-pool Pa per graph + head MLP
    pool_head_kernel<<<NG, 64>>>(batch, Wf, bf, Wl, bl, out);
}